// round 6
// baseline (speedup 1.0000x reference)
#include <cuda_runtime.h>

typedef unsigned long long u64;
typedef unsigned int u32;

#define IMG_W 2048
#define IMG_H 2048
#define NWORDS 32               // 32 x u64 = 2048 bits per column
#define NPIX (IMG_W * IMG_H)
#define COFF 8                  // column padding: prefetch never bounds-checks
#define NCOLS (IMG_W + 2 * COFF)
#define BLK 33                  // columns per producer/consumer block
#define NBLK 62                 // 62 * 33 = 2046 interior columns
#define SLOTS (BLK * 32)

// Interleaved bit grids, column-major: elem (c, w) = {A, L} for 64 rows.
// d_AL: canonical row order. d_ALr: reversed rows (brevll + word swap).
__device__ ulonglong2 d_AL [NCOLS * NWORDS];
__device__ ulonglong2 d_ALr[NCOLS * NWORDS];

// ---------------------------------------------------------------------------
// Fused: low/high outputs + bitpack {A = thin>=3, L = thin>=1}, both grids.
// ---------------------------------------------------------------------------
__global__ void k_prep(const float* __restrict__ thin, float* __restrict__ out) {
    int c = blockIdx.x * 32 + threadIdx.x;
    int w = blockIdx.y * blockDim.y + threadIdx.y;
    u64 L = 0, A = 0;
    size_t base = (size_t)(w * 64) * IMG_W + c;
    #pragma unroll 8
    for (int b = 0; b < 64; ++b) {
        size_t idx = base + (size_t)b * IMG_W;
        float v = thin[idx];
        bool lo = (v >= 1.0f), hi = (v >= 3.0f);
        out[idx]        = lo ? v : 0.0f;   // low
        out[NPIX + idx] = hi ? v : 0.0f;   // high
        L |= ((u64)lo) << b;
        A |= ((u64)hi) << b;
    }
    d_AL [(c + COFF) * NWORDS + w]        = make_ulonglong2(A, L);
    d_ALr[(c + COFF) * NWORDS + (31 - w)] = make_ulonglong2(__brevll(A), __brevll(L));
}

// ---------------------------------------------------------------------------
// One directional pass, warp-specialized:
//   warp0 = scan producer: gated-or scan (carry chain of p+g), publishes
//           {side, mid} per column into a double-buffered smem ring.
//   warp1 = store consumer: one block behind, rebuilds Ap/Ac rolling state
//           from the ring and does all stores (+ its own prefetch).
// Handshake: one __syncthreads() per 33-column block (double buffering).
// CROSS: stores go to the OTHER grid at word 31-lane with brevll.
// ---------------------------------------------------------------------------
template <bool XR, bool CROSS>
__device__ __forceinline__ void pass_run(int tid, ulonglong2* ring,
                                         const ulonglong2* __restrict__ ldg,
                                         ulonglong2* __restrict__ stg) {
    const u32 FULL = 0xffffffffu;
    const int lane = tid & 31;
    const int dx = XR ? -1 : 1;
    const int dxs = XR ? -NWORDS : NWORDS;     // column stride (ulonglong2)
    const int cx0 = XR ? (IMG_W - 2) : 1;
    const ulonglong2* lbase = ldg + lane;

    if (tid < 32) {
        // ----------------- warp0: scan producer -----------------
        u64 INTM = ~0ull;
        if (lane == 0)  INTM &= ~1ull;                   // virtual row 0
        if (lane == 31) INTM &= 0x7fffffffffffffffull;   // virtual row 2047
        const u32 notTop = (lane == 31) ? 0u : ~0u;

        ulonglong2 v;
        v = lbase[(size_t)(cx0 + COFF) * NWORDS];
        u64 gc = v.x & INTM, pc = v.y & INTM;
        v = lbase[(size_t)(cx0 + dx + COFF) * NWORDS];
        u64 AnM = v.x & INTM, LnM = v.y & INTM;
        u64 rA[3], rL[3];
        #pragma unroll
        for (int u = 0; u < 3; ++u) {
            v = lbase[(size_t)(cx0 + (2 + u) * dx + COFF) * NWORDS];
            rA[u] = v.x; rL[u] = v.y;
        }
        const ulonglong2* ldp = lbase + (size_t)(cx0 + 5 * dx + COFF) * NWORDS;

        for (int k = 0; k < NBLK; ++k) {
            ulonglong2* rp = ring + (k & 1) * SLOTS + lane;
            #pragma unroll 1
            for (int it = 0; it < 11; ++it) {
                #pragma unroll
                for (int u = 0; u < 3; ++u) {
                    u32 b0  = ((u32)gc & 1u) | (((u32)pc << 1) & 2u);
                    u32 b0n = __shfl_down_sync(FULL, b0, 1) & notTop;
                    u64 pxg = pc ^ gc;
                    u64 sum0 = pc + gc;
                    u64 sum1 = sum0 + 1;
                    u32 G = __ballot_sync(FULL, sum0 < pc);
                    u32 P = __ballot_sync(FULL, sum0 == ~0ull);
                    u64 cb0 = sum0 ^ pxg;
                    u64 cb1 = sum1 ^ pxg;
                    u32 C  = (P + G) ^ (P ^ G);     // cin per lane (bit32 provably 0)
                    u32 Cs = C >> lane;             // bit0 = cin, bit1 = cout
                    u64 cb = (Cs & 1u) ? cb1 : cb0; // carry-in bits == dn
                    u64 t  = cb | (cb >> 2);
                    u32 co = Cs & 2u;
                    u32 s0n = (b0n & 1u) | ((b0n >> 1) & (Cs >> 1) & 1u);
                    u32 hm = (co << 29) | (s0n << 31);   // ->bits 62, 63
                    u32 hs = hm | (co << 30);            // + ->bit 63
                    u64 mid  = t | ((u64)hm << 32);
                    u64 side = t | (cb >> 1) | ((u64)hs << 32);
                    rp[0] = make_ulonglong2(side, mid);
                    rp += 32;
                    gc = AnM | (side & LnM);             // critical recurrence
                    pc = LnM;
                    AnM = rA[u] & INTM; LnM = rL[u] & INTM;
                    ulonglong2 pf = ldp[0]; ldp += dxs;  // padded: no bounds check
                    rA[u] = pf.x; rL[u] = pf.y;
                }
            }
            __syncthreads();     // publish block k
        }
        __syncthreads();         // wait for consumer tail
    } else {
        // ----------------- warp1: store consumer -----------------
        u64* stp;
        {
            int widx = CROSS ? (31 - lane) : lane;
            stp = (u64*)stg + 2 * ((size_t)(cx0 - dx + COFF) * NWORDS + widx);
        }
        const int dst = 2 * dxs;

        ulonglong2 v;
        v = lbase[(size_t)(cx0 - dx + COFF) * NWORDS];
        u64 Ap = v.x, Lp = v.y;
        v = lbase[(size_t)(cx0 + COFF) * NWORDS];
        u64 Ac = v.x, Lc = v.y;
        v = lbase[(size_t)(cx0 + dx + COFF) * NWORDS];
        u64 An = v.x, Ln = v.y;
        u64 rA[3], rL[3];
        #pragma unroll
        for (int u = 0; u < 3; ++u) {
            v = lbase[(size_t)(cx0 + (2 + u) * dx + COFF) * NWORDS];
            rA[u] = v.x; rL[u] = v.y;
        }
        const ulonglong2* ldp = lbase + (size_t)(cx0 + 5 * dx + COFF) * NWORDS;

        for (int k = 0; k < NBLK; ++k) {
            __syncthreads();     // block k published by warp0
            const ulonglong2* rp = ring + (k & 1) * SLOTS + lane;
            #pragma unroll 1
            for (int it = 0; it < 11; ++it) {
                #pragma unroll
                for (int u = 0; u < 3; ++u) {
                    ulonglong2 sm = rp[0]; rp += 32;
                    u64 side = sm.x, mid = sm.y;
                    u64 stv = Ap | (side & Lp);          // final for col cx-dx
                    stp[0] = CROSS ? __brevll(stv) : stv;
                    stp += dst;
                    Ap = Ac | (mid & Lc);  Lp = Lc;
                    Ac = An | (side & Ln); Lc = Ln;
                    An = rA[u]; Ln = rL[u];
                    ulonglong2 pf = ldp[0]; ldp += dxs;
                    rA[u] = pf.x; rL[u] = pf.y;
                }
            }
        }
        // flush last two columns
        stp[0] = CROSS ? __brevll(Ap) : Ap; stp += dst;
        stp[0] = CROSS ? __brevll(Ac) : Ac;
        __syncthreads();
    }
}

__global__ void __launch_bounds__(64, 1) k_trace() {
    __shared__ ulonglong2 ring[2 * SLOTS];    // 33 KB double-buffered {side,mid}
    int tid = threadIdx.x;
    // p1 (F,F): read AL,  write ALr (cross)
    pass_run<false, true >(tid, ring, d_AL,  d_ALr);
    // p2 (T,T): read/write ALr
    pass_run<true,  false>(tid, ring, d_ALr, d_ALr);
    // p3 (F,T): read ALr, write AL (cross)
    pass_run<false, true >(tid, ring, d_ALr, d_AL);
    // p4 (T,F): read/write AL
    pass_run<true,  false>(tid, ring, d_AL,  d_AL);
}

// ---------------------------------------------------------------------------
// final = A ? thin : 0. Tile 64 rows x 32 cols; thread owns one column-word,
// writes 8 coalesced pixels.
// ---------------------------------------------------------------------------
__global__ void k_final(const float* __restrict__ thin, float* __restrict__ out) {
    int c0 = blockIdx.x * 32;
    int r0 = blockIdx.y * 64;
    int lane = threadIdx.x & 31;
    int sub  = threadIdx.x >> 5;      // 0..7
    u64 wrd = d_AL[(c0 + lane + COFF) * NWORDS + (r0 >> 6)].x;
    #pragma unroll
    for (int k = 0; k < 8; ++k) {
        int rr = sub * 8 + k;
        size_t idx = (size_t)(r0 + rr) * IMG_W + c0 + lane;
        bool act = (wrd >> rr) & 1ull;
        out[2 * NPIX + idx] = act ? thin[idx] : 0.0f;
    }
}

// ---------------------------------------------------------------------------
extern "C" void kernel_launch(void* const* d_in, const int* in_sizes, int n_in,
                              void* d_out, int out_size) {
    const float* thin = (const float*)d_in[0];
    float* out = (float*)d_out;

    dim3 bpB(32, 8);
    dim3 bpG(IMG_W / 32, NWORDS / 8);
    k_prep<<<bpG, bpB>>>(thin, out);

    k_trace<<<1, 64>>>();

    dim3 fG(IMG_W / 32, IMG_H / 64);
    k_final<<<fG, 256>>>(thin, out);
}

// round 7
// speedup vs baseline: 1.7089x; 1.7089x over previous
#include <cuda_runtime.h>

typedef unsigned long long u64;
typedef unsigned int u32;

#define IMG_W 2048
#define IMG_H 2048
#define NWORDS 32               // 32 x u64 = 2048 bits per column
#define NPIX (IMG_W * IMG_H)
#define COFF 8                  // column padding: prefetch never bounds-checks
#define NCOLS (IMG_W + 2 * COFF)

// Interleaved bit grids, column-major: elem (c, w) = {A, L} for 64 rows.
// d_AL: canonical row order. d_ALr: reversed rows (brevll + word swap).
__device__ ulonglong2 d_AL [NCOLS * NWORDS];
__device__ ulonglong2 d_ALr[NCOLS * NWORDS];

// ---------------------------------------------------------------------------
// Fused: low/high outputs + bitpack {A = thin>=3, L = thin>=1}, both grids.
// ---------------------------------------------------------------------------
__global__ void k_prep(const float* __restrict__ thin, float* __restrict__ out) {
    int c = blockIdx.x * 32 + threadIdx.x;
    int w = blockIdx.y * blockDim.y + threadIdx.y;
    u64 L = 0, A = 0;
    size_t base = (size_t)(w * 64) * IMG_W + c;
    #pragma unroll 8
    for (int b = 0; b < 64; ++b) {
        size_t idx = base + (size_t)b * IMG_W;
        float v = thin[idx];
        bool lo = (v >= 1.0f), hi = (v >= 3.0f);
        out[idx]        = lo ? v : 0.0f;   // low
        out[NPIX + idx] = hi ? v : 0.0f;   // high
        L |= ((u64)lo) << b;
        A |= ((u64)hi) << b;
    }
    d_AL [(c + COFF) * NWORDS + w]        = make_ulonglong2(A, L);
    d_ALr[(c + COFF) * NWORDS + (31 - w)] = make_ulonglong2(__brevll(A), __brevll(L));
}

// ---------------------------------------------------------------------------
// One directional trace pass, single warp. Lane k owns 64 virtual rows in the
// stored orientation of the load grid (no brev on any load).
// Gated-or scan s_i = g_i | (p_i & s_{i-1}) == carry chain of p+g (g subset p).
// Cross-lane carries: 2 ballots + one scalar 32-bit carry add.
// dn == cb; s == cb>>1 | cout<<63; mid = cb|cb>>2|hi; side = mid|cb>>1|hi.
// CROSS: stores go to the OTHER grid at word 31-lane with brevll (off-chain).
// ---------------------------------------------------------------------------
template <bool XR, bool CROSS>
__device__ __forceinline__ void trace_pass(const int lane,
                                           const ulonglong2* __restrict__ ldg,
                                           ulonglong2* __restrict__ stg) {
    const u32 FULL = 0xffffffffu;
    u64 INTM = ~0ull;
    if (lane == 0)  INTM &= ~1ull;                   // virtual row 0
    if (lane == 31) INTM &= 0x7fffffffffffffffull;   // virtual row 2047
    const u32 notTop = (lane == 31) ? 0u : ~0u;

    const int dx  = XR ? -1 : 1;
    const int dxs = XR ? -NWORDS : NWORDS;           // column stride in ulonglong2
    const int cx0 = XR ? (IMG_W - 2) : 1;

    const ulonglong2* lbase = ldg + lane;
    u64* stp;
    {
        int widx = CROSS ? (31 - lane) : lane;
        stp = (u64*)(stg + (size_t)(cx0 - dx + COFF) * NWORDS + widx);
    }
    const int dst = 2 * dxs;                         // store stride in u64

    ulonglong2 v;
    v = lbase[(size_t)(cx0 - dx + COFF) * NWORDS];
    u64 Ap = v.x, Lp = v.y;
    v = lbase[(size_t)(cx0 + COFF) * NWORDS];
    u64 Ac = v.x, Lc = v.y;
    v = lbase[(size_t)(cx0 + dx + COFF) * NWORDS];
    u64 An = v.x, Ln = v.y;
    u64 gc = Ac & INTM, pc = Lc & INTM;
    u64 rA[6], rL[6];
    #pragma unroll
    for (int j = 0; j < 6; ++j) {
        v = lbase[(size_t)(cx0 + (2 + j) * dx + COFF) * NWORDS];
        rA[j] = v.x; rL[j] = v.y;
    }
    const ulonglong2* ldp = lbase + (size_t)(cx0 + 8 * dx + COFF) * NWORDS;

    #pragma unroll 1
    for (int blk = 0; blk < (IMG_W - 2) / 6; ++blk) {      // 341 x 6 = 2046
        #pragma unroll
        for (int j = 0; j < 6; ++j) {
            // off-chain: next-lane bit0 info
            u32 b0  = ((u32)gc & 1u) | (((u32)pc << 1) & 2u);
            u32 b0n = __shfl_down_sync(FULL, b0, 1) & notTop;
            u64 pxg = pc ^ gc;
            u64 sum0 = pc + gc;
            u64 sum1 = sum0 + 1;
            u32 G = __ballot_sync(FULL, sum0 < pc);        // lane carry-gen
            u32 P = __ballot_sync(FULL, sum0 == ~0ull);    // lane carry-prop
            u64 cb0 = sum0 ^ pxg;                          // speculative cin=0
            u64 cb1 = sum1 ^ pxg;                          // speculative cin=1
            u32 C  = (P + G) ^ (P ^ G);     // cin per lane (bit32 provably 0)
            u32 Cs = C >> lane;             // bit0 = cin, bit1 = cout
            u64 cb = (Cs & 1u) ? cb1 : cb0; // carry-in bits == dn
            u64 t  = cb | (cb >> 2);
            u32 co = Cs & 2u;
            u32 s0n = (b0n & 1u) | ((b0n >> 1) & (Cs >> 1) & 1u);
            u32 hm = (co << 29) | (s0n << 31);   // cout->bit62, s0n->bit63
            u32 hs = hm | (co << 30);            // + cout->bit63
            u64 mid  = t | ((u64)hm << 32);
            u64 side = t | (cb >> 1) | ((u64)hs << 32);

            u64 stv = Ap | (side & Lp);          // final for col cx-dx
            stp[0] = CROSS ? __brevll(stv) : stv;
            stp += dst;
            Ap = Ac | (mid & Lc);  Lp = Lc;
            Ac = An | (side & Ln);
            gc = Ac & INTM;                      // critical recurrence
            pc = Ln & INTM;
            Lc = Ln;
            An = rA[j]; Ln = rL[j];
            ulonglong2 pf = ldp[0]; ldp += dxs;  // padded: no bounds check
            rA[j] = pf.x; rL[j] = pf.y;
        }
    }
    stp[0] = CROSS ? __brevll(Ap) : Ap; stp += dst;
    stp[0] = CROSS ? __brevll(Ac) : Ac;
}

__global__ void __launch_bounds__(32, 1) k_trace() {
    const int lane = threadIdx.x;
    // p1 (F,F): read AL,  write ALr (cross)
    trace_pass<false, true >(lane, d_AL,  d_ALr);
    __threadfence_block(); __syncwarp();
    // p2 (T,T): read/write ALr
    trace_pass<true,  false>(lane, d_ALr, d_ALr);
    __threadfence_block(); __syncwarp();
    // p3 (F,T): read ALr, write AL (cross)
    trace_pass<false, true >(lane, d_ALr, d_AL);
    __threadfence_block(); __syncwarp();
    // p4 (T,F): read/write AL
    trace_pass<true,  false>(lane, d_AL,  d_AL);
}

// ---------------------------------------------------------------------------
// final = A ? thin : 0. Tile 64 rows x 32 cols; thread owns one column-word,
// writes 8 coalesced pixels.
// ---------------------------------------------------------------------------
__global__ void k_final(const float* __restrict__ thin, float* __restrict__ out) {
    int c0 = blockIdx.x * 32;
    int r0 = blockIdx.y * 64;
    int lane = threadIdx.x & 31;
    int sub  = threadIdx.x >> 5;      // 0..7
    u64 wrd = d_AL[(c0 + lane + COFF) * NWORDS + (r0 >> 6)].x;
    #pragma unroll
    for (int k = 0; k < 8; ++k) {
        int rr = sub * 8 + k;
        size_t idx = (size_t)(r0 + rr) * IMG_W + c0 + lane;
        bool act = (wrd >> rr) & 1ull;
        out[2 * NPIX + idx] = act ? thin[idx] : 0.0f;
    }
}

// ---------------------------------------------------------------------------
extern "C" void kernel_launch(void* const* d_in, const int* in_sizes, int n_in,
                              void* d_out, int out_size) {
    const float* thin = (const float*)d_in[0];
    float* out = (float*)d_out;

    dim3 bpB(32, 8);
    dim3 bpG(IMG_W / 32, NWORDS / 8);
    k_prep<<<bpG, bpB>>>(thin, out);

    k_trace<<<1, 32>>>();

    dim3 fG(IMG_W / 32, IMG_H / 64);
    k_final<<<fG, 256>>>(thin, out);
}